// round 2
// baseline (speedup 1.0000x reference)
#include <cuda_runtime.h>
#include <cstdint>

// Problem constants (fixed shapes from reference setup_inputs)
#define Bn 8
#define Cc 3
#define Hh 540
#define Ww 960
#define HW (Hh * Ww)
#define EPSV 1e-6f
// log2(1.414) computed in double: 0.49978707423949623
#define LOG2_WB 0.49978707423949623f
#define NT 256

// Scratch: global min of disp, stored as float bits (disp >= 0 so uint order == float order)
__device__ unsigned int g_min_bits;

__global__ void init_min_kernel() {
    g_min_bits = 0x7F800000u; // +inf
}

__global__ void reduce_min_kernel(const float4* __restrict__ disp4, int n4) {
    float m = __int_as_float(0x7F800000); // +inf
    int stride = gridDim.x * blockDim.x;
    for (int i = blockIdx.x * blockDim.x + threadIdx.x; i < n4; i += stride) {
        float4 v = disp4[i];
        m = fminf(m, fminf(fminf(v.x, v.y), fminf(v.z, v.w)));
    }
    // warp reduce
    #pragma unroll
    for (int o = 16; o > 0; o >>= 1)
        m = fminf(m, __shfl_xor_sync(0xFFFFFFFFu, m, o));
    __shared__ float sm[32];
    int lane = threadIdx.x & 31;
    int wid  = threadIdx.x >> 5;
    if (lane == 0) sm[wid] = m;
    __syncthreads();
    if (wid == 0) {
        int nwarps = blockDim.x >> 5;
        m = (lane < nwarps) ? sm[lane] : __int_as_float(0x7F800000);
        #pragma unroll
        for (int o = 16; o > 0; o >>= 1)
            m = fminf(m, __shfl_xor_sync(0xFFFFFFFFu, m, o));
        if (lane == 0)
            atomicMin(&g_min_bits, __float_as_uint(m));
    }
}

// One CTA per (b, y) row. Horizontal-only splat (flow_y == 0).
__global__ __launch_bounds__(NT) void splat_row_kernel(
    const float* __restrict__ im,
    const float* __restrict__ disp,
    float* __restrict__ out)
{
    __shared__ float s_r0[Ww];
    __shared__ float s_r1[Ww];
    __shared__ float s_r2[Ww];
    __shared__ float s_mk[Ww];
    __shared__ float s_oc[Ww];

    const int row = blockIdx.x;           // 0 .. Bn*Hh-1
    const int b = row / Hh;
    const int y = row - b * Hh;
    const int tid = threadIdx.x;

    // zero accumulators
    #pragma unroll
    for (int i = tid; i < Ww; i += NT) {
        s_r0[i] = 0.f; s_r1[i] = 0.f; s_r2[i] = 0.f;
        s_mk[i] = 0.f; s_oc[i] = 0.f;
    }
    const float dmin = __uint_as_float(g_min_bits);
    __syncthreads();

    const float* dptr = disp + (b * Hh + y) * Ww;
    const float* i0 = im + ((b * Cc + 0) * Hh + y) * Ww;
    const float* i1 = i0 + HW;
    const float* i2 = i1 + HW;

    #pragma unroll
    for (int x = tid; x < Ww; x += NT) {
        const float d  = dptr[x];
        const float wm = exp2f((d - dmin) * LOG2_WB);
        const float xf = (float)x - d;
        const float x0 = floorf(xf);
        const float wx1 = xf - x0;          // weight toward x0+1
        int   xi = (int)x0;

        const float v0 = i0[x] * wm;
        const float v1 = i1[x] * wm;
        const float v2 = i2[x] * wm;

        float w = 1.f - wx1;
        if (xi >= 0 && xi < Ww) {
            atomicAdd(&s_r0[xi], v0 * w);
            atomicAdd(&s_r1[xi], v1 * w);
            atomicAdd(&s_r2[xi], v2 * w);
            atomicAdd(&s_mk[xi], wm * w);
            atomicAdd(&s_oc[xi], w);
        }
        xi += 1;
        w = wx1;
        if (xi >= 0 && xi < Ww) {
            atomicAdd(&s_r0[xi], v0 * w);
            atomicAdd(&s_r1[xi], v1 * w);
            atomicAdd(&s_r2[xi], v2 * w);
            atomicAdd(&s_mk[xi], wm * w);
            atomicAdd(&s_oc[xi], w);
        }
    }
    __syncthreads();

    float* o0  = out + ((b * Cc + 0) * Hh + y) * Ww;
    float* o1  = o0 + HW;
    float* o2  = o1 + HW;
    float* ooc = out + (size_t)Bn * Cc * HW + (b * Hh + y) * Ww;

    #pragma unroll
    for (int x = tid; x < Ww; x += NT) {
        const float mk = fmaxf(s_mk[x], EPSV);
        const float inv = 1.f / mk;
        o0[x] = s_r0[x] * inv;
        o1[x] = s_r1[x] * inv;
        o2[x] = s_r2[x] * inv;
        float oc = s_oc[x];
        oc = fminf(fmaxf(oc, 0.f), 1.f);
        ooc[x] = 1.f - oc;
    }
}

extern "C" void kernel_launch(void* const* d_in, const int* in_sizes, int n_in,
                              void* d_out, int out_size)
{
    const float* im   = (const float*)d_in[0];   // [8,3,540,960]
    const float* disp = (const float*)d_in[1];   // [8,1,540,960]
    float* out = (float*)d_out;                   // res [8,3,H,W] then occlu [8,1,H,W]

    init_min_kernel<<<1, 1>>>();

    const int n4 = (Bn * HW) / 4;                 // 1,036,800 float4s
    reduce_min_kernel<<<1024, 256>>>((const float4*)disp, n4);

    splat_row_kernel<<<Bn * Hh, NT>>>(im, disp, out);
}

// round 3
// speedup vs baseline: 1.0729x; 1.0729x over previous
#include <cuda_runtime.h>
#include <cstdint>

// Fixed shapes from reference setup_inputs
#define Bn 8
#define Cc 3
#define Hh 540
#define Ww 960
#define HW (Hh * Ww)
#define EPSV 1e-6f
// log2(1.414)
#define LOG2_WB 0.49978707423949623f
#define NT 256
#define NQ (Ww / 4)   // 240 quads per row

// Single fused kernel: one CTA per (b,y) row. Horizontal-only splat (flow_y == 0).
// dmin normalization dropped: it cancels in res = accum/mask (see analysis);
// occlusion uses splat(ones), unaffected.
__global__ __launch_bounds__(NT) void splat_row_kernel(
    const float* __restrict__ im,
    const float* __restrict__ disp,
    float* __restrict__ out)
{
    __shared__ __align__(16) float sacc[5 * Ww];
    float* s_r0 = sacc;
    float* s_r1 = sacc + Ww;
    float* s_r2 = sacc + 2 * Ww;
    float* s_mk = sacc + 3 * Ww;
    float* s_oc = sacc + 4 * Ww;

    const int row = blockIdx.x;           // 0 .. Bn*Hh-1
    const int b = row / Hh;
    const int y = row - b * Hh;
    const int tid = threadIdx.x;

    // zero accumulators (5*960 floats = 1200 float4)
    {
        float4 z = make_float4(0.f, 0.f, 0.f, 0.f);
        float4* sz = (float4*)sacc;
        #pragma unroll
        for (int i = tid; i < 5 * NQ; i += NT) sz[i] = z;
    }
    __syncthreads();

    const float4* d4  = (const float4*)(disp + (size_t)row * Ww);
    const float4* a04 = (const float4*)(im + ((size_t)(b * Cc + 0) * Hh + y) * Ww);
    const float4* a14 = a04 + HW / 4;
    const float4* a24 = a14 + HW / 4;

    if (tid < NQ) {
        const float4 dv = d4[tid];
        const float4 c0 = a04[tid];
        const float4 c1 = a14[tid];
        const float4 c2 = a24[tid];
        const int xb = tid * 4;

        const float dd_[4] = {dv.x, dv.y, dv.z, dv.w};
        const float p0_[4] = {c0.x, c0.y, c0.z, c0.w};
        const float p1_[4] = {c1.x, c1.y, c1.z, c1.w};
        const float p2_[4] = {c2.x, c2.y, c2.z, c2.w};

        #pragma unroll
        for (int k = 0; k < 4; k++) {
            const float d  = dd_[k];
            const float wm = exp2f(d * LOG2_WB);
            const float xf = (float)(xb + k) - d;
            const float x0 = floorf(xf);
            const float wx1 = xf - x0;          // weight toward x0+1
            const int   xi  = (int)x0;

            const float v0 = p0_[k] * wm;
            const float v1 = p1_[k] * wm;
            const float v2 = p2_[k] * wm;

            // corner 0: xi <= x always (d >= 0), only left bound can fail
            float w = 1.f - wx1;
            if (xi >= 0) {
                atomicAdd(&s_r0[xi], v0 * w);
                atomicAdd(&s_r1[xi], v1 * w);
                atomicAdd(&s_r2[xi], v2 * w);
                atomicAdd(&s_mk[xi], wm * w);
                atomicAdd(&s_oc[xi], w);
            }
            // corner 1
            const int xj = xi + 1;
            w = wx1;
            if (xj >= 0 && xj < Ww) {
                atomicAdd(&s_r0[xj], v0 * w);
                atomicAdd(&s_r1[xj], v1 * w);
                atomicAdd(&s_r2[xj], v2 * w);
                atomicAdd(&s_mk[xj], wm * w);
                atomicAdd(&s_oc[xj], w);
            }
        }
    }
    __syncthreads();

    // epilogue: normalize + occlusion, vectorized
    float4* o0  = (float4*)(out + ((size_t)(b * Cc + 0) * Hh + y) * Ww);
    float4* o1  = o0 + HW / 4;
    float4* o2  = o1 + HW / 4;
    float4* ooc = (float4*)(out + (size_t)Bn * Cc * HW + (size_t)row * Ww);

    const float4* sr0 = (const float4*)s_r0;
    const float4* sr1 = (const float4*)s_r1;
    const float4* sr2 = (const float4*)s_r2;
    const float4* smk = (const float4*)s_mk;
    const float4* soc = (const float4*)s_oc;

    if (tid < NQ) {
        const float4 mk = smk[tid];
        float4 inv;
        inv.x = 1.f / fmaxf(mk.x, EPSV);
        inv.y = 1.f / fmaxf(mk.y, EPSV);
        inv.z = 1.f / fmaxf(mk.z, EPSV);
        inv.w = 1.f / fmaxf(mk.w, EPSV);

        float4 r = sr0[tid];
        r.x *= inv.x; r.y *= inv.y; r.z *= inv.z; r.w *= inv.w;
        o0[tid] = r;
        r = sr1[tid];
        r.x *= inv.x; r.y *= inv.y; r.z *= inv.z; r.w *= inv.w;
        o1[tid] = r;
        r = sr2[tid];
        r.x *= inv.x; r.y *= inv.y; r.z *= inv.z; r.w *= inv.w;
        o2[tid] = r;

        float4 oc = soc[tid];
        oc.x = 1.f - fminf(fmaxf(oc.x, 0.f), 1.f);
        oc.y = 1.f - fminf(fmaxf(oc.y, 0.f), 1.f);
        oc.z = 1.f - fminf(fmaxf(oc.z, 0.f), 1.f);
        oc.w = 1.f - fminf(fmaxf(oc.w, 0.f), 1.f);
        ooc[tid] = oc;
    }
}

extern "C" void kernel_launch(void* const* d_in, const int* in_sizes, int n_in,
                              void* d_out, int out_size)
{
    const float* im   = (const float*)d_in[0];   // [8,3,540,960]
    const float* disp = (const float*)d_in[1];   // [8,1,540,960]
    float* out = (float*)d_out;                   // res [8,3,H,W] then occlu [8,1,H,W]

    splat_row_kernel<<<Bn * Hh, NT>>>(im, disp, out);
}